// round 9
// baseline (speedup 1.0000x reference)
#include <cuda_runtime.h>
#include <cuda_bf16.h>
#include <cstddef>
#include <cstdint>

#define N_NODES 65536
#define KTAPS   27
#define COUT    128
#define BN_EPS  1e-3f

// ==================== helpers ====================
__device__ __forceinline__ uint32_t smem_to_u32(const void* p) {
    uint32_t a;
    asm("{ .reg .u64 t; cvta.to.shared.u64 t, %1; cvt.u32.u64 %0, t; }" : "=r"(a) : "l"(p));
    return a;
}
__device__ __forceinline__ void ldsm_x4(uint32_t& r0, uint32_t& r1, uint32_t& r2, uint32_t& r3,
                                        uint32_t addr) {
    asm volatile("ldmatrix.sync.aligned.m8n8.x4.shared.b16 {%0,%1,%2,%3}, [%4];"
                 : "=r"(r0), "=r"(r1), "=r"(r2), "=r"(r3) : "r"(addr));
}
__device__ __forceinline__ void mma_bf16(float* c, const uint32_t* a, const uint32_t* b) {
    asm volatile(
        "mma.sync.aligned.m16n8k16.row.col.f32.bf16.bf16.f32 "
        "{%0,%1,%2,%3}, {%4,%5,%6,%7}, {%8,%9}, {%0,%1,%2,%3};"
        : "+f"(c[0]), "+f"(c[1]), "+f"(c[2]), "+f"(c[3])
        : "r"(a[0]), "r"(a[1]), "r"(a[2]), "r"(a[3]), "r"(b[0]), "r"(b[1]));
}
__device__ __forceinline__ void cp16(uint32_t s, const void* g) {
    asm volatile("{ .reg .u64 gg; cvta.to.global.u64 gg, %1;"
                 "  cp.async.cg.shared.global [%0], [gg], 16; }"
                 :: "r"(s), "l"(g) : "memory");
}
#define CP_COMMIT() asm volatile("cp.async.commit_group;" ::: "memory")
#define CP_WAIT1()  asm volatile("cp.async.wait_group 1;" ::: "memory")
#define CP_WAIT0()  asm volatile("cp.async.wait_group 0;" ::: "memory")

// ==================== scratch (static device memory; no allocs) ====================
__device__ __nv_bfloat16 g_xhi[(size_t)N_NODES * 64];
__device__ __nv_bfloat16 g_xlo[(size_t)N_NODES * 64];
__device__ __nv_bfloat16 g_wa_hi[(size_t)KTAPS * 2 * 128 * 32];
__device__ __nv_bfloat16 g_wa_lo[(size_t)KTAPS * 2 * 128 * 32];
__device__ __nv_bfloat16 g_wb_hi[(size_t)KTAPS * 4 * 128 * 32];
__device__ __nv_bfloat16 g_wb_lo[(size_t)KTAPS * 4 * 128 * 32];
__device__ __nv_bfloat16 g_ws_hi[(size_t)2 * 128 * 32];
__device__ __nv_bfloat16 g_ws_lo[(size_t)2 * 128 * 32];
__device__ float g_ya[(size_t)N_NODES * COUT];            // conv_a out fp32, node-major
__device__ __nv_bfloat16 g_yahi[(size_t)N_NODES * COUT];  // relu(BN_a(ya)) split
__device__ __nv_bfloat16 g_yalo[(size_t)N_NODES * COUT];
__device__ float g_yb[(size_t)COUT * N_NODES];            // conv_b out, ch-major
__device__ float g_sk[(size_t)COUT * N_NODES];            // skip out,  ch-major
__device__ float g_stat[2 * COUT];
__device__ float g_scale_a[COUT];
__device__ float g_bias_a[COUT];
__device__ float g_coef[4 * COUT];

// ==================== tiny: zero stat accumulators ====================
__global__ void zero_stat_kernel(float* acc) { acc[threadIdx.x] = 0.f; }

// ==================== x transpose + bf16 hi/lo split ====================
__global__ void xsplit_kernel(const float* __restrict__ x,
                              __nv_bfloat16* __restrict__ xhi,
                              __nv_bfloat16* __restrict__ xlo) {
    __shared__ float tile[32][33];
    int nb = blockIdx.x * 32, cb = blockIdx.y * 32;
    int tx = threadIdx.x, ty = threadIdx.y;
#pragma unroll
    for (int i = 0; i < 4; i++)
        tile[ty + i * 8][tx] = x[(size_t)(cb + ty + i * 8) * N_NODES + nb + tx];
    __syncthreads();
#pragma unroll
    for (int i = 0; i < 4; i++) {
        float v = tile[tx][ty + i * 8];
        __nv_bfloat16 h = __float2bfloat16(v);
        size_t idx = (size_t)(nb + ty + i * 8) * 64 + cb + tx;
        xhi[idx] = h;
        xlo[idx] = __float2bfloat16(v - __bfloat162float(h));
    }
}

// ==================== weight transpose + split: w[o][c][k] -> [k][ch32][o][c32] ====================
__global__ void wsplit_kernel(const float* __restrict__ w,
                              __nv_bfloat16* __restrict__ whi,
                              __nv_bfloat16* __restrict__ wlo,
                              int C, int K) {
    int i = blockIdx.x * 256 + threadIdx.x;
    int total = 128 * C * K;
    if (i >= total) return;
    int CH = C / 32;
    int cl = i & 31;
    int o  = (i >> 5) & 127;
    int kc = i >> 12;
    int ch = kc % CH;
    int k  = kc / CH;
    int c  = ch * 32 + cl;
    float v = w[((size_t)o * C + c) * K + k];
    __nv_bfloat16 h = __float2bfloat16(v);
    whi[i] = h;
    wlo[i] = __float2bfloat16(v - __bfloat162float(h));
}

// ==================== gathered conv GEMM on HMMA ====================
// 4 warps, warp tile 64x64, CC=32 chunks, 2-stage cp.async ring, 2 CTAs/SM.
// Race-free: compute-complete barrier BEFORE re-issuing into a ring buffer.
// 3-pass bf16 split (hi*hi + lo*hi + hi*lo), fp32 register accumulators.
template<int CIN, int KT, bool GATHER, bool CHMAJOR>
__global__ __launch_bounds__(128, 2)
void tconv_kernel(const __nv_bfloat16* __restrict__ src_hi,
                  const __nv_bfloat16* __restrict__ src_lo,
                  const __nv_bfloat16* __restrict__ w_hi,
                  const __nv_bfloat16* __restrict__ w_lo,
                  const int* __restrict__ neigh,
                  float* __restrict__ out) {
    constexpr int CH = CIN / 32;
    constexpr int STEPS = KT * CH;
    constexpr int RS = 80;                       // conflict-free row stride
    constexpr uint32_t AH = 0, AL = 10240, WH = 20480, WL = 30720, BUF = 40960;
    extern __shared__ __align__(16) char smem[];
    const uint32_t sb = smem_to_u32(smem);

    const int t = threadIdx.x;
    const int lane = t & 31, wid = t >> 5;
    const int n_base = blockIdx.x * 128;
    const int warp_m = (wid & 1) * 64;
    const int warp_n = (wid >> 1) * 64;
    const uint32_t aoff_lane = (uint32_t)(warp_m + (lane & 15)) * RS + ((lane & 16) ? 16u : 0u);
    const uint32_t boff_lane = (uint32_t)(warp_n + (lane & 7) + ((lane & 16) ? 8 : 0)) * RS
                               + ((lane & 8) ? 16u : 0u);

    float acc[4][8][4];
#pragma unroll
    for (int mi = 0; mi < 4; mi++)
#pragma unroll
        for (int ni = 0; ni < 8; ni++)
#pragma unroll
            for (int e = 0; e < 4; e++) acc[mi][ni][e] = 0.f;

    auto j_of = [&](int s) -> int {
        return GATHER ? neigh[(size_t)(n_base + t) * KT + (s / CH)] : (n_base + t);
    };

    auto issue = [&](int s, int j) {
        const uint32_t stg = sb + (uint32_t)(s & 1) * BUF;
        const int k = s / CH, ch = s % CH;
        // activations: thread t fills row t (32 ch = 64 B, hi + lo)
        const __nv_bfloat16* ah = src_hi + (size_t)j * CIN + ch * 32;
        const __nv_bfloat16* al = src_lo + (size_t)j * CIN + ch * 32;
        const uint32_t ab = stg + AH + (uint32_t)t * RS;
        const uint32_t lb = stg + AL + (uint32_t)t * RS;
#pragma unroll
        for (int i = 0; i < 4; i++) {
            cp16(ab + i * 16, ah + i * 8);
            cp16(lb + i * 16, al + i * 8);
        }
        // weights: thread t fills out-row t (32 ch = 64 B, hi + lo)
        const __nv_bfloat16* wh = w_hi + ((size_t)(k * CH + ch) << 12) + t * 32;
        const __nv_bfloat16* wl = w_lo + ((size_t)(k * CH + ch) << 12) + t * 32;
        const uint32_t wbh = stg + WH + (uint32_t)t * RS;
        const uint32_t wbl = stg + WL + (uint32_t)t * RS;
#pragma unroll
        for (int i = 0; i < 4; i++) {
            cp16(wbh + i * 16, wh + i * 8);
            cp16(wbl + i * 16, wl + i * 8);
        }
        CP_COMMIT();
    };

    // prologue: fill both ring stages
    {
        int j0 = j_of(0);
        issue(0, j0);
        if (STEPS > 1) {
            int j1 = j_of(1);
            issue(1, j1);
        }
    }
    int jn = (STEPS > 2) ? j_of(2) : 0;

    for (int s = 0; s < STEPS; ++s) {
        if (s + 1 < STEPS) CP_WAIT1(); else CP_WAIT0();
        __syncthreads();                          // stage s visible to all warps

        const uint32_t sbuf = sb + (uint32_t)(s & 1) * BUF;

#pragma unroll
        for (int k16 = 0; k16 < 2; ++k16) {
            const uint32_t kb = (uint32_t)k16 * 32;
            const uint32_t a_h = sbuf + AH + aoff_lane + kb;
            const uint32_t a_l = sbuf + AL + aoff_lane + kb;
            const uint32_t b_h = sbuf + WH + boff_lane + kb;
            const uint32_t b_l = sbuf + WL + boff_lane + kb;

            uint32_t ah[4][4], bh[8][2];
#pragma unroll
            for (int mi = 0; mi < 4; mi++)
                ldsm_x4(ah[mi][0], ah[mi][1], ah[mi][2], ah[mi][3], a_h + mi * (16 * RS));
#pragma unroll
            for (int nt = 0; nt < 4; nt++) {
                uint32_t r0, r1, r2, r3;
                ldsm_x4(r0, r1, r2, r3, b_h + nt * (16 * RS));
                bh[2 * nt][0] = r0; bh[2 * nt][1] = r1;
                bh[2 * nt + 1][0] = r2; bh[2 * nt + 1][1] = r3;
            }
#pragma unroll
            for (int mi = 0; mi < 4; mi++)
#pragma unroll
                for (int ni = 0; ni < 8; ni++)
                    mma_bf16(acc[mi][ni], ah[mi], bh[ni]);
            {   // pass 2: lo(act) * hi(w)
                uint32_t al4[4][4];
#pragma unroll
                for (int mi = 0; mi < 4; mi++)
                    ldsm_x4(al4[mi][0], al4[mi][1], al4[mi][2], al4[mi][3],
                            a_l + mi * (16 * RS));
#pragma unroll
                for (int mi = 0; mi < 4; mi++)
#pragma unroll
                    for (int ni = 0; ni < 8; ni++)
                        mma_bf16(acc[mi][ni], al4[mi], bh[ni]);
            }
            {   // pass 3: hi(act) * lo(w)
                uint32_t bl[8][2];
#pragma unroll
                for (int nt = 0; nt < 4; nt++) {
                    uint32_t r0, r1, r2, r3;
                    ldsm_x4(r0, r1, r2, r3, b_l + nt * (16 * RS));
                    bl[2 * nt][0] = r0; bl[2 * nt][1] = r1;
                    bl[2 * nt + 1][0] = r2; bl[2 * nt + 1][1] = r3;
                }
#pragma unroll
                for (int mi = 0; mi < 4; mi++)
#pragma unroll
                    for (int ni = 0; ni < 8; ni++)
                        mma_bf16(acc[mi][ni], ah[mi], bl[ni]);
            }
        }

        // refill the buffer we just consumed — only after ALL warps finished it
        if (s + 2 < STEPS) {
            __syncthreads();                      // compute-complete barrier (race fix)
            issue(s + 2, jn);
            if (s + 3 < STEPS) jn = j_of(s + 3);
        }
    }

    // ---- epilogue ----
#pragma unroll
    for (int mi = 0; mi < 4; mi++)
#pragma unroll
        for (int ni = 0; ni < 8; ni++) {
            int r = n_base + warp_m + mi * 16 + (lane >> 2);
            int c = warp_n + ni * 8 + (lane & 3) * 2;
            if (CHMAJOR) {
                out[(size_t)c * N_NODES + r]           = acc[mi][ni][0];
                out[(size_t)(c + 1) * N_NODES + r]     = acc[mi][ni][1];
                out[(size_t)c * N_NODES + r + 8]       = acc[mi][ni][2];
                out[(size_t)(c + 1) * N_NODES + r + 8] = acc[mi][ni][3];
            } else {
                *(float2*)&out[(size_t)r * COUT + c] =
                    make_float2(acc[mi][ni][0], acc[mi][ni][1]);
                *(float2*)&out[(size_t)(r + 8) * COUT + c] =
                    make_float2(acc[mi][ni][2], acc[mi][ni][3]);
            }
        }
}

// ==================== BN_a stats: coalesced partial sums + atomics ====================
__global__ void stats_nm_kernel(const float* __restrict__ y, float* __restrict__ acc) {
    const int t = threadIdx.x;
    const int c = t & 127, half = t >> 7;
    const int nb = blockIdx.x * 1024;
    float s = 0.f, q = 0.f;
    for (int n = nb + half; n < nb + 1024; n += 2) {
        float v = y[(size_t)n * COUT + c];
        s += v; q += v * v;
    }
    __shared__ float rs[256], rq[256];
    rs[t] = s; rq[t] = q;
    __syncthreads();
    if (half == 0) {
        atomicAdd(&acc[c],        rs[t] + rs[t + 128]);
        atomicAdd(&acc[COUT + c], rq[t] + rq[t + 128]);
    }
}

// ==================== BN_a finalize ====================
__global__ void stats_fin_kernel(const float* __restrict__ acc,
                                 const float* __restrict__ gamma,
                                 const float* __restrict__ beta,
                                 float* __restrict__ scale,
                                 float* __restrict__ bias) {
    int c = threadIdx.x;
    float mean = acc[c] / N_NODES;
    float var  = acc[COUT + c] / N_NODES - mean * mean;
    float kk   = gamma[c] * rsqrtf(var + BN_EPS);
    scale[c] = kk;
    bias[c]  = beta[c] - kk * mean;
}

// ==================== yasplit: relu(BN_a(ya)) -> bf16 hi/lo ====================
__global__ void yasplit_kernel(const float* __restrict__ ya,
                               const float* __restrict__ scale,
                               const float* __restrict__ bias,
                               __nv_bfloat16* __restrict__ yhi,
                               __nv_bfloat16* __restrict__ ylo) {
    int i = blockIdx.x * 256 + threadIdx.x;      // quad index
    int c0 = (i & 31) * 4;
    float4 v  = ((const float4*)ya)[i];
    float4 sc = *(const float4*)(scale + c0);
    float4 bi = *(const float4*)(bias + c0);
    float a0 = fmaxf(fmaf(v.x, sc.x, bi.x), 0.f);
    float a1 = fmaxf(fmaf(v.y, sc.y, bi.y), 0.f);
    float a2 = fmaxf(fmaf(v.z, sc.z, bi.z), 0.f);
    float a3 = fmaxf(fmaf(v.w, sc.w, bi.w), 0.f);
    __nv_bfloat16 h0 = __float2bfloat16(a0), h1 = __float2bfloat16(a1);
    __nv_bfloat16 h2 = __float2bfloat16(a2), h3 = __float2bfloat16(a3);
    ((__nv_bfloat162*)yhi)[i * 2]     = __nv_bfloat162(h0, h1);
    ((__nv_bfloat162*)yhi)[i * 2 + 1] = __nv_bfloat162(h2, h3);
    ((__nv_bfloat162*)ylo)[i * 2]     = __floats2bfloat162_rn(a0 - __bfloat162float(h0),
                                                              a1 - __bfloat162float(h1));
    ((__nv_bfloat162*)ylo)[i * 2 + 1] = __floats2bfloat162_rn(a2 - __bfloat162float(h2),
                                                              a3 - __bfloat162float(h3));
}

// ==================== BN stats over ch-major yb & sk ====================
__global__ void stats_om_kernel(const float* __restrict__ yb,
                                const float* __restrict__ sk,
                                const float* __restrict__ gb,
                                const float* __restrict__ bb,
                                const float* __restrict__ gs,
                                const float* __restrict__ bs,
                                float* __restrict__ coef) {
    int c = blockIdx.x;
    const float4* pb = (const float4*)(yb + (size_t)c * N_NODES);
    const float4* ps = (const float4*)(sk + (size_t)c * N_NODES);
    float s1 = 0.f, q1 = 0.f, s2 = 0.f, q2 = 0.f;
    for (int i = threadIdx.x; i < N_NODES / 4; i += 256) {
        float4 a = pb[i];
        s1 += a.x + a.y + a.z + a.w;
        q1 += a.x * a.x + a.y * a.y + a.z * a.z + a.w * a.w;
        float4 b = ps[i];
        s2 += b.x + b.y + b.z + b.w;
        q2 += b.x * b.x + b.y * b.y + b.z * b.z + b.w * b.w;
    }
    __shared__ float r1[256], r2[256], r3[256], r4[256];
    r1[threadIdx.x] = s1; r2[threadIdx.x] = q1;
    r3[threadIdx.x] = s2; r4[threadIdx.x] = q2;
    __syncthreads();
    for (int st = 128; st > 0; st >>= 1) {
        if (threadIdx.x < st) {
            r1[threadIdx.x] += r1[threadIdx.x + st];
            r2[threadIdx.x] += r2[threadIdx.x + st];
            r3[threadIdx.x] += r3[threadIdx.x + st];
            r4[threadIdx.x] += r4[threadIdx.x + st];
        }
        __syncthreads();
    }
    if (threadIdx.x == 0) {
        float m1 = r1[0] / N_NODES, v1 = r2[0] / N_NODES - m1 * m1;
        float k1 = gb[c] * rsqrtf(v1 + BN_EPS);
        coef[c]            = k1;
        coef[COUT + c]     = bb[c] - k1 * m1;
        float m2 = r3[0] / N_NODES, v2 = r4[0] / N_NODES - m2 * m2;
        float k2 = gs[c] * rsqrtf(v2 + BN_EPS);
        coef[2 * COUT + c] = k2;
        coef[3 * COUT + c] = bs[c] - k2 * m2;
    }
}

// ==================== final: out = relu(BN_b(yb) + BN_s(sk)) ====================
__global__ void final_ew_kernel(const float* __restrict__ yb,
                                const float* __restrict__ sk,
                                const float* __restrict__ coef,
                                float* __restrict__ out) {
    int i = blockIdx.x * 256 + threadIdx.x;
    int o = i >> 14;
    float sb = coef[o],            bb = coef[COUT + o];
    float ss = coef[2 * COUT + o], bs = coef[3 * COUT + o];
    float4 a = ((const float4*)yb)[i];
    float4 b = ((const float4*)sk)[i];
    float4 r;
    r.x = fmaxf(fmaf(sb, a.x, bb) + fmaf(ss, b.x, bs), 0.f);
    r.y = fmaxf(fmaf(sb, a.y, bb) + fmaf(ss, b.y, bs), 0.f);
    r.z = fmaxf(fmaf(sb, a.z, bb) + fmaf(ss, b.z, bs), 0.f);
    r.w = fmaxf(fmaf(sb, a.w, bb) + fmaf(ss, b.w, bs), 0.f);
    ((float4*)out)[i] = r;
}

// ==================== host ====================
static constexpr int TCONV_SMEM = 2 * 40960;   // 81920 B -> 2 CTAs/SM

extern "C" void kernel_launch(void* const* d_in, const int* in_sizes, int n_in,
                              void* d_out, int out_size) {
    const float* data    = (const float*)d_in[0];
    const int*   neigh   = (const int*)  d_in[1];
    const float* w_a     = (const float*)d_in[2];
    const float* w_b     = (const float*)d_in[3];
    const float* w_skip  = (const float*)d_in[4];
    const float* gamma_a = (const float*)d_in[5];
    const float* beta_a  = (const float*)d_in[6];
    const float* gamma_b = (const float*)d_in[7];
    const float* beta_b  = (const float*)d_in[8];
    const float* gamma_s = (const float*)d_in[9];
    const float* beta_s  = (const float*)d_in[10];
    float* out = (float*)d_out;

    __nv_bfloat16 *xhi, *xlo, *wah, *wal, *wbh, *wbl, *wsh, *wsl, *yahi, *yalo;
    float *ya, *yb, *sk, *stat, *sca, *bia, *coef;
    cudaGetSymbolAddress((void**)&xhi,  g_xhi);
    cudaGetSymbolAddress((void**)&xlo,  g_xlo);
    cudaGetSymbolAddress((void**)&wah,  g_wa_hi);
    cudaGetSymbolAddress((void**)&wal,  g_wa_lo);
    cudaGetSymbolAddress((void**)&wbh,  g_wb_hi);
    cudaGetSymbolAddress((void**)&wbl,  g_wb_lo);
    cudaGetSymbolAddress((void**)&wsh,  g_ws_hi);
    cudaGetSymbolAddress((void**)&wsl,  g_ws_lo);
    cudaGetSymbolAddress((void**)&ya,   g_ya);
    cudaGetSymbolAddress((void**)&yahi, g_yahi);
    cudaGetSymbolAddress((void**)&yalo, g_yalo);
    cudaGetSymbolAddress((void**)&yb,   g_yb);
    cudaGetSymbolAddress((void**)&sk,   g_sk);
    cudaGetSymbolAddress((void**)&stat, g_stat);
    cudaGetSymbolAddress((void**)&sca,  g_scale_a);
    cudaGetSymbolAddress((void**)&bia,  g_bias_a);
    cudaGetSymbolAddress((void**)&coef, g_coef);

    auto* ka = tconv_kernel<64, KTAPS, true, false>;
    auto* kb = tconv_kernel<128, KTAPS, true, true>;
    auto* ks = tconv_kernel<64, 1, false, true>;
    cudaFuncSetAttribute(ka, cudaFuncAttributeMaxDynamicSharedMemorySize, TCONV_SMEM);
    cudaFuncSetAttribute(kb, cudaFuncAttributeMaxDynamicSharedMemorySize, TCONV_SMEM);
    cudaFuncSetAttribute(ks, cudaFuncAttributeMaxDynamicSharedMemorySize, TCONV_SMEM);

    // layout transforms + precision splits
    zero_stat_kernel<<<1, 256>>>(stat);
    xsplit_kernel<<<dim3(N_NODES / 32, 2), dim3(32, 8)>>>(data, xhi, xlo);
    wsplit_kernel<<<(KTAPS * 64 * 128 + 255) / 256, 256>>>(w_a, wah, wal, 64, KTAPS);
    wsplit_kernel<<<(KTAPS * 128 * 128 + 255) / 256, 256>>>(w_b, wbh, wbl, 128, KTAPS);
    wsplit_kernel<<<(64 * 128 + 255) / 256, 256>>>(w_skip, wsh, wsl, 64, 1);

    const int grid = N_NODES / 128;   // 512

    // conv_a (HMMA), node-major fp32 out
    ka<<<grid, 128, TCONV_SMEM>>>(xhi, xlo, wah, wal, neigh, ya);
    // BN_a stats + finalize + split c1 to bf16 hi/lo
    stats_nm_kernel<<<64, 256>>>(ya, stat);
    stats_fin_kernel<<<1, 128>>>(stat, gamma_a, beta_a, sca, bia);
    yasplit_kernel<<<(N_NODES * COUT / 4) / 256, 256>>>(ya, sca, bia, yahi, yalo);
    // conv_b (HMMA, presplit gathered input), ch-major out
    kb<<<grid, 128, TCONV_SMEM>>>(yahi, yalo, wbh, wbl, neigh, yb);
    // skip (HMMA, no gather), ch-major out
    ks<<<grid, 128, TCONV_SMEM>>>(xhi, xlo, wsh, wsl, nullptr, sk);
    // BN_b + BN_s stats
    stats_om_kernel<<<COUT, 256>>>(yb, sk, gamma_b, beta_b, gamma_s, beta_s, coef);
    // final elementwise
    final_ew_kernel<<<(COUT * N_NODES / 4) / 256, 256>>>(yb, sk, coef, out);
}

// round 10
// speedup vs baseline: 1.0283x; 1.0283x over previous
#include <cuda_runtime.h>
#include <cuda_fp16.h>
#include <cstddef>
#include <cstdint>

#define N_NODES 65536
#define KTAPS   27
#define COUT    128
#define BN_EPS  1e-3f

// ==================== helpers ====================
__device__ __forceinline__ uint32_t smem_to_u32(const void* p) {
    uint32_t a;
    asm("{ .reg .u64 t; cvta.to.shared.u64 t, %1; cvt.u32.u64 %0, t; }" : "=r"(a) : "l"(p));
    return a;
}
__device__ __forceinline__ void ldsm_x4(uint32_t& r0, uint32_t& r1, uint32_t& r2, uint32_t& r3,
                                        uint32_t addr) {
    asm volatile("ldmatrix.sync.aligned.m8n8.x4.shared.b16 {%0,%1,%2,%3}, [%4];"
                 : "=r"(r0), "=r"(r1), "=r"(r2), "=r"(r3) : "r"(addr));
}
__device__ __forceinline__ void mma_f16(float* c, const uint32_t* a, const uint32_t* b) {
    asm volatile(
        "mma.sync.aligned.m16n8k16.row.col.f32.f16.f16.f32 "
        "{%0,%1,%2,%3}, {%4,%5,%6,%7}, {%8,%9}, {%0,%1,%2,%3};"
        : "+f"(c[0]), "+f"(c[1]), "+f"(c[2]), "+f"(c[3])
        : "r"(a[0]), "r"(a[1]), "r"(a[2]), "r"(a[3]), "r"(b[0]), "r"(b[1]));
}
__device__ __forceinline__ void cp16(uint32_t s, const void* g) {
    asm volatile("{ .reg .u64 gg; cvta.to.global.u64 gg, %1;"
                 "  cp.async.cg.shared.global [%0], [gg], 16; }"
                 :: "r"(s), "l"(g) : "memory");
}
#define CP_COMMIT() asm volatile("cp.async.commit_group;" ::: "memory")
#define CP_WAIT1()  asm volatile("cp.async.wait_group 1;" ::: "memory")
#define CP_WAIT0()  asm volatile("cp.async.wait_group 0;" ::: "memory")

// ==================== scratch (static device memory; no allocs) ====================
__device__ __half g_xhi[(size_t)N_NODES * 64];
__device__ __half g_xlo[(size_t)N_NODES * 64];
__device__ __half g_wa16[(size_t)KTAPS * 128 * 64];       // [k][o][c64]
__device__ __half g_wb16[(size_t)KTAPS * 2 * 128 * 64];   // [k][ch][o][c64]
__device__ __half g_ws16[(size_t)128 * 64];
__device__ float  g_ya[(size_t)N_NODES * COUT];           // conv_a out fp32, node-major
__device__ __half g_yahi[(size_t)N_NODES * COUT];         // relu(BN_a(ya)) split
__device__ __half g_yalo[(size_t)N_NODES * COUT];
__device__ float  g_yb[(size_t)COUT * N_NODES];           // conv_b out, ch-major
__device__ float  g_sk[(size_t)COUT * N_NODES];           // skip out,  ch-major
__device__ float  g_stat[2 * COUT];
__device__ float  g_scale_a[COUT];
__device__ float  g_bias_a[COUT];
__device__ float  g_coef[4 * COUT];

// ==================== tiny: zero stat accumulators ====================
__global__ void zero_stat_kernel(float* acc) { acc[threadIdx.x] = 0.f; }

// ==================== x transpose + fp16 hi/lo split ====================
__global__ void xsplit_kernel(const float* __restrict__ x,
                              __half* __restrict__ xhi,
                              __half* __restrict__ xlo) {
    __shared__ float tile[32][33];
    int nb = blockIdx.x * 32, cb = blockIdx.y * 32;
    int tx = threadIdx.x, ty = threadIdx.y;
#pragma unroll
    for (int i = 0; i < 4; i++)
        tile[ty + i * 8][tx] = x[(size_t)(cb + ty + i * 8) * N_NODES + nb + tx];
    __syncthreads();
#pragma unroll
    for (int i = 0; i < 4; i++) {
        float v = tile[tx][ty + i * 8];
        __half h = __float2half_rn(v);
        size_t idx = (size_t)(nb + ty + i * 8) * 64 + cb + tx;
        xhi[idx] = h;
        xlo[idx] = __float2half_rn(v - __half2float(h));
    }
}

// ==================== weight convert: w[o][c][k] -> fp16 [k][ch64][o][c64] ====================
__global__ void wconv_kernel(const float* __restrict__ w,
                             __half* __restrict__ w16,
                             int C, int K) {
    int i = blockIdx.x * 256 + threadIdx.x;
    int total = 128 * C * K;
    if (i >= total) return;
    int CH = C / 64;
    int cl = i & 63;
    int o  = (i >> 6) & 127;
    int kc = i >> 13;
    int ch = kc % CH;
    int k  = kc / CH;
    int c  = ch * 64 + cl;
    w16[i] = __float2half_rn(w[((size_t)o * C + c) * K + k]);
}

// ==================== gathered conv GEMM on HMMA (fp16, 2-pass) ====================
// D[node, out] = sum_{k,c} act[node,k,c] * w[out,k,c]
// act split hi/lo fp16 (2 MMA passes), weights single fp16. 8 warps, warp tile 64x32,
// CC=64 chunk, 3-stage cp.async ring.
template<int CIN, int KT, bool GATHER, bool CHMAJOR>
__global__ __launch_bounds__(256, 1)
void tconv_kernel(const __half* __restrict__ src_hi,
                  const __half* __restrict__ src_lo,
                  const __half* __restrict__ w16,
                  const int* __restrict__ neigh,
                  float* __restrict__ out) {
    constexpr int CH = CIN / 64;
    constexpr int STEPS = KT * CH;
    constexpr int RS = 144;                       // 128 B row + 16 pad
    constexpr uint32_t AH = 0, AL = 18432, WH = 36864, BUF = 55296;
    extern __shared__ __align__(16) char smem[];
    const uint32_t sb = smem_to_u32(smem);

    const int t = threadIdx.x;
    const int lane = t & 31, wid = t >> 5;
    const int n_base = blockIdx.x * 128;
    const int warp_m = (wid & 1) * 64;
    const int warp_n = (wid >> 1) * 32;
    const uint32_t aoff_lane = (uint32_t)(warp_m + (lane & 15)) * RS + ((lane & 16) ? 16u : 0u);
    const uint32_t boff_lane = (uint32_t)(warp_n + (lane & 7) + ((lane & 16) ? 8 : 0)) * RS
                               + ((lane & 8) ? 16u : 0u);

    const int row = t >> 1, part = t & 1;

    float acc[4][4][4];
#pragma unroll
    for (int mi = 0; mi < 4; mi++)
#pragma unroll
        for (int ni = 0; ni < 4; ni++)
#pragma unroll
            for (int e = 0; e < 4; e++) acc[mi][ni][e] = 0.f;

    auto j_of = [&](int s) -> int {
        return GATHER ? neigh[(size_t)(n_base + row) * KT + (s / CH)] : (n_base + row);
    };

    auto issue = [&](int s, int j) {
        const uint32_t stg = sb + (uint32_t)(s % 3) * BUF;
        const int k = s / CH, ch = s % CH;
        // activations hi/lo: row `row`, this thread covers 64 B (32 halfs)
        const __half* ah = src_hi + (size_t)j * CIN + ch * 64 + part * 32;
        const __half* al = src_lo + (size_t)j * CIN + ch * 64 + part * 32;
        const uint32_t ab = stg + AH + (uint32_t)row * RS + part * 64;
        const uint32_t lb = stg + AL + (uint32_t)row * RS + part * 64;
#pragma unroll
        for (int i = 0; i < 4; i++) {
            cp16(ab + i * 16, ah + i * 8);
            cp16(lb + i * 16, al + i * 8);
        }
        // weights (single fp16): out-row `row`, 64 B
        const __half* wp = w16 + ((size_t)(k * CH + ch) << 13) + row * 64 + part * 32;
        const uint32_t wb = stg + WH + (uint32_t)row * RS + part * 64;
#pragma unroll
        for (int i = 0; i < 4; i++)
            cp16(wb + i * 16, wp + i * 8);
        CP_COMMIT();
    };

    int jn = j_of(0);
    issue(0, jn);
    if (STEPS > 1) jn = j_of(1);

    for (int s = 0; s < STEPS; ++s) {
        if (s + 1 < STEPS) {
            issue(s + 1, jn);                    // writes buf (s+1)%3 — safe at depth 3
            if (s + 2 < STEPS) jn = j_of(s + 2);
            CP_WAIT1();
        } else {
            CP_WAIT0();
        }
        __syncthreads();

        const uint32_t sbuf = sb + (uint32_t)(s % 3) * BUF;

#pragma unroll
        for (int k16 = 0; k16 < 4; ++k16) {
            const uint32_t kb = (uint32_t)k16 * 32;
            const uint32_t a_h = sbuf + AH + aoff_lane + kb;
            const uint32_t a_l = sbuf + AL + aoff_lane + kb;
            const uint32_t b_h = sbuf + WH + boff_lane + kb;

            uint32_t ah[4][4], bh[4][2];
#pragma unroll
            for (int mi = 0; mi < 4; mi++)
                ldsm_x4(ah[mi][0], ah[mi][1], ah[mi][2], ah[mi][3], a_h + mi * (16 * RS));
#pragma unroll
            for (int nt = 0; nt < 2; nt++) {
                uint32_t r0, r1, r2, r3;
                ldsm_x4(r0, r1, r2, r3, b_h + nt * (16 * RS));
                bh[2 * nt][0] = r0; bh[2 * nt][1] = r1;
                bh[2 * nt + 1][0] = r2; bh[2 * nt + 1][1] = r3;
            }
            // pass 1: hi(act) * w
#pragma unroll
            for (int mi = 0; mi < 4; mi++)
#pragma unroll
                for (int ni = 0; ni < 4; ni++)
                    mma_f16(acc[mi][ni], ah[mi], bh[ni]);
            // pass 2: lo(act) * w
            {
                uint32_t al4[4][4];
#pragma unroll
                for (int mi = 0; mi < 4; mi++)
                    ldsm_x4(al4[mi][0], al4[mi][1], al4[mi][2], al4[mi][3],
                            a_l + mi * (16 * RS));
#pragma unroll
                for (int mi = 0; mi < 4; mi++)
#pragma unroll
                    for (int ni = 0; ni < 4; ni++)
                        mma_f16(acc[mi][ni], al4[mi], bh[ni]);
            }
        }
    }

    // ---- epilogue ----
#pragma unroll
    for (int mi = 0; mi < 4; mi++)
#pragma unroll
        for (int ni = 0; ni < 4; ni++) {
            int r = n_base + warp_m + mi * 16 + (lane >> 2);
            int c = warp_n + ni * 8 + (lane & 3) * 2;
            if (CHMAJOR) {
                out[(size_t)c * N_NODES + r]           = acc[mi][ni][0];
                out[(size_t)(c + 1) * N_NODES + r]     = acc[mi][ni][1];
                out[(size_t)c * N_NODES + r + 8]       = acc[mi][ni][2];
                out[(size_t)(c + 1) * N_NODES + r + 8] = acc[mi][ni][3];
            } else {
                *(float2*)&out[(size_t)r * COUT + c] =
                    make_float2(acc[mi][ni][0], acc[mi][ni][1]);
                *(float2*)&out[(size_t)(r + 8) * COUT + c] =
                    make_float2(acc[mi][ni][2], acc[mi][ni][3]);
            }
        }
}

// ==================== BN_a stats: coalesced partial sums + atomics ====================
__global__ void stats_nm_kernel(const float* __restrict__ y, float* __restrict__ acc) {
    const int t = threadIdx.x;
    const int c = t & 127, half = t >> 7;
    const int nb = blockIdx.x * 1024;
    float s = 0.f, q = 0.f;
    for (int n = nb + half; n < nb + 1024; n += 2) {
        float v = y[(size_t)n * COUT + c];
        s += v; q += v * v;
    }
    __shared__ float rs[256], rq[256];
    rs[t] = s; rq[t] = q;
    __syncthreads();
    if (half == 0) {
        atomicAdd(&acc[c],        rs[t] + rs[t + 128]);
        atomicAdd(&acc[COUT + c], rq[t] + rq[t + 128]);
    }
}

// ==================== BN_a finalize ====================
__global__ void stats_fin_kernel(const float* __restrict__ acc,
                                 const float* __restrict__ gamma,
                                 const float* __restrict__ beta,
                                 float* __restrict__ scale,
                                 float* __restrict__ bias) {
    int c = threadIdx.x;
    float mean = acc[c] / N_NODES;
    float var  = acc[COUT + c] / N_NODES - mean * mean;
    float kk   = gamma[c] * rsqrtf(var + BN_EPS);
    scale[c] = kk;
    bias[c]  = beta[c] - kk * mean;
}

// ==================== yasplit: relu(BN_a(ya)) -> fp16 hi/lo ====================
__global__ void yasplit_kernel(const float* __restrict__ ya,
                               const float* __restrict__ scale,
                               const float* __restrict__ bias,
                               __half* __restrict__ yhi,
                               __half* __restrict__ ylo) {
    int i = blockIdx.x * 256 + threadIdx.x;      // quad index
    int c0 = (i & 31) * 4;
    float4 v  = ((const float4*)ya)[i];
    float4 sc = *(const float4*)(scale + c0);
    float4 bi = *(const float4*)(bias + c0);
    float a0 = fmaxf(fmaf(v.x, sc.x, bi.x), 0.f);
    float a1 = fmaxf(fmaf(v.y, sc.y, bi.y), 0.f);
    float a2 = fmaxf(fmaf(v.z, sc.z, bi.z), 0.f);
    float a3 = fmaxf(fmaf(v.w, sc.w, bi.w), 0.f);
    __half h0 = __float2half_rn(a0), h1 = __float2half_rn(a1);
    __half h2 = __float2half_rn(a2), h3 = __float2half_rn(a3);
    ((__half2*)yhi)[i * 2]     = __half2(h0, h1);
    ((__half2*)yhi)[i * 2 + 1] = __half2(h2, h3);
    ((__half2*)ylo)[i * 2]     = __floats2half2_rn(a0 - __half2float(h0),
                                                   a1 - __half2float(h1));
    ((__half2*)ylo)[i * 2 + 1] = __floats2half2_rn(a2 - __half2float(h2),
                                                   a3 - __half2float(h3));
}

// ==================== BN stats over ch-major yb & sk ====================
__global__ void stats_om_kernel(const float* __restrict__ yb,
                                const float* __restrict__ sk,
                                const float* __restrict__ gb,
                                const float* __restrict__ bb,
                                const float* __restrict__ gs,
                                const float* __restrict__ bs,
                                float* __restrict__ coef) {
    int c = blockIdx.x;
    const float4* pb = (const float4*)(yb + (size_t)c * N_NODES);
    const float4* ps = (const float4*)(sk + (size_t)c * N_NODES);
    float s1 = 0.f, q1 = 0.f, s2 = 0.f, q2 = 0.f;
    for (int i = threadIdx.x; i < N_NODES / 4; i += 256) {
        float4 a = pb[i];
        s1 += a.x + a.y + a.z + a.w;
        q1 += a.x * a.x + a.y * a.y + a.z * a.z + a.w * a.w;
        float4 b = ps[i];
        s2 += b.x + b.y + b.z + b.w;
        q2 += b.x * b.x + b.y * b.y + b.z * b.z + b.w * b.w;
    }
    __shared__ float r1[256], r2[256], r3[256], r4[256];
    r1[threadIdx.x] = s1; r2[threadIdx.x] = q1;
    r3[threadIdx.x] = s2; r4[threadIdx.x] = q2;
    __syncthreads();
    for (int st = 128; st > 0; st >>= 1) {
        if (threadIdx.x < st) {
            r1[threadIdx.x] += r1[threadIdx.x + st];
            r2[threadIdx.x] += r2[threadIdx.x + st];
            r3[threadIdx.x] += r3[threadIdx.x + st];
            r4[threadIdx.x] += r4[threadIdx.x + st];
        }
        __syncthreads();
    }
    if (threadIdx.x == 0) {
        float m1 = r1[0] / N_NODES, v1 = r2[0] / N_NODES - m1 * m1;
        float k1 = gb[c] * rsqrtf(v1 + BN_EPS);
        coef[c]            = k1;
        coef[COUT + c]     = bb[c] - k1 * m1;
        float m2 = r3[0] / N_NODES, v2 = r4[0] / N_NODES - m2 * m2;
        float k2 = gs[c] * rsqrtf(v2 + BN_EPS);
        coef[2 * COUT + c] = k2;
        coef[3 * COUT + c] = bs[c] - k2 * m2;
    }
}

// ==================== final: out = relu(BN_b(yb) + BN_s(sk)) ====================
__global__ void final_ew_kernel(const float* __restrict__ yb,
                                const float* __restrict__ sk,
                                const float* __restrict__ coef,
                                float* __restrict__ out) {
    int i = blockIdx.x * 256 + threadIdx.x;
    int o = i >> 14;
    float sb = coef[o],            bb = coef[COUT + o];
    float ss = coef[2 * COUT + o], bs = coef[3 * COUT + o];
    float4 a = ((const float4*)yb)[i];
    float4 b = ((const float4*)sk)[i];
    float4 r;
    r.x = fmaxf(fmaf(sb, a.x, bb) + fmaf(ss, b.x, bs), 0.f);
    r.y = fmaxf(fmaf(sb, a.y, bb) + fmaf(ss, b.y, bs), 0.f);
    r.z = fmaxf(fmaf(sb, a.z, bb) + fmaf(ss, b.z, bs), 0.f);
    r.w = fmaxf(fmaf(sb, a.w, bb) + fmaf(ss, b.w, bs), 0.f);
    ((float4*)out)[i] = r;
}

// ==================== host ====================
static constexpr int TCONV_SMEM = 3 * 55296;   // 165888 B

extern "C" void kernel_launch(void* const* d_in, const int* in_sizes, int n_in,
                              void* d_out, int out_size) {
    const float* data    = (const float*)d_in[0];
    const int*   neigh   = (const int*)  d_in[1];
    const float* w_a     = (const float*)d_in[2];
    const float* w_b     = (const float*)d_in[3];
    const float* w_skip  = (const float*)d_in[4];
    const float* gamma_a = (const float*)d_in[5];
    const float* beta_a  = (const float*)d_in[6];
    const float* gamma_b = (const float*)d_in[7];
    const float* beta_b  = (const float*)d_in[8];
    const float* gamma_s = (const float*)d_in[9];
    const float* beta_s  = (const float*)d_in[10];
    float* out = (float*)d_out;

    __half *xhi, *xlo, *wa16, *wb16, *ws16, *yahi, *yalo;
    float *ya, *yb, *sk, *stat, *sca, *bia, *coef;
    cudaGetSymbolAddress((void**)&xhi,  g_xhi);
    cudaGetSymbolAddress((void**)&xlo,  g_xlo);
    cudaGetSymbolAddress((void**)&wa16, g_wa16);
    cudaGetSymbolAddress((void**)&wb16, g_wb16);
    cudaGetSymbolAddress((void**)&ws16, g_ws16);
    cudaGetSymbolAddress((void**)&ya,   g_ya);
    cudaGetSymbolAddress((void**)&yahi, g_yahi);
    cudaGetSymbolAddress((void**)&yalo, g_yalo);
    cudaGetSymbolAddress((void**)&yb,   g_yb);
    cudaGetSymbolAddress((void**)&sk,   g_sk);
    cudaGetSymbolAddress((void**)&stat, g_stat);
    cudaGetSymbolAddress((void**)&sca,  g_scale_a);
    cudaGetSymbolAddress((void**)&bia,  g_bias_a);
    cudaGetSymbolAddress((void**)&coef, g_coef);

    auto* ka = tconv_kernel<64, KTAPS, true, false>;
    auto* kb = tconv_kernel<128, KTAPS, true, true>;
    auto* ks = tconv_kernel<64, 1, false, true>;
    cudaFuncSetAttribute(ka, cudaFuncAttributeMaxDynamicSharedMemorySize, TCONV_SMEM);
    cudaFuncSetAttribute(kb, cudaFuncAttributeMaxDynamicSharedMemorySize, TCONV_SMEM);
    cudaFuncSetAttribute(ks, cudaFuncAttributeMaxDynamicSharedMemorySize, TCONV_SMEM);

    // layout transforms + precision splits
    zero_stat_kernel<<<1, 256>>>(stat);
    xsplit_kernel<<<dim3(N_NODES / 32, 2), dim3(32, 8)>>>(data, xhi, xlo);
    wconv_kernel<<<(KTAPS * 64 * 128 + 255) / 256, 256>>>(w_a, wa16, 64, KTAPS);
    wconv_kernel<<<(KTAPS * 128 * 128 + 255) / 256, 256>>>(w_b, wb16, 128, KTAPS);
    wconv_kernel<<<(64 * 128 + 255) / 256, 256>>>(w_skip, ws16, 64, 1);

    const int grid = N_NODES / 128;   // 512

    // conv_a (HMMA fp16 2-pass), node-major fp32 out
    ka<<<grid, 256, TCONV_SMEM>>>(xhi, xlo, wa16, neigh, ya);
    // BN_a stats + finalize + split c1 to fp16 hi/lo
    stats_nm_kernel<<<64, 256>>>(ya, stat);
    stats_fin_kernel<<<1, 128>>>(stat, gamma_a, beta_a, sca, bia);
    yasplit_kernel<<<(N_NODES * COUT / 4) / 256, 256>>>(ya, sca, bia, yahi, yalo);
    // conv_b, ch-major out
    kb<<<grid, 256, TCONV_SMEM>>>(yahi, yalo, wb16, neigh, yb);
    // skip, ch-major out
    ks<<<grid, 256, TCONV_SMEM>>>(xhi, xlo, ws16, nullptr, sk);
    // BN_b + BN_s stats
    stats_om_kernel<<<COUT, 256>>>(yb, sk, gamma_b, beta_b, gamma_s, beta_s, coef);
    // final elementwise
    final_ew_kernel<<<(COUT * N_NODES / 4) / 256, 256>>>(yb, sk, coef, out);
}

// round 11
// speedup vs baseline: 2.3290x; 2.2650x over previous
#include <cuda_runtime.h>
#include <cuda_fp16.h>
#include <cstddef>
#include <cstdint>

#define N_NODES 65536
#define KTAPS   27
#define COUT    128
#define BN_EPS  1e-3f

// ==================== helpers ====================
__device__ __forceinline__ uint32_t smem_to_u32(const void* p) {
    uint32_t a;
    asm("{ .reg .u64 t; cvta.to.shared.u64 t, %1; cvt.u32.u64 %0, t; }" : "=r"(a) : "l"(p));
    return a;
}
__device__ __forceinline__ void ldsm_x4(uint32_t& r0, uint32_t& r1, uint32_t& r2, uint32_t& r3,
                                        uint32_t addr) {
    asm volatile("ldmatrix.sync.aligned.m8n8.x4.shared.b16 {%0,%1,%2,%3}, [%4];"
                 : "=r"(r0), "=r"(r1), "=r"(r2), "=r"(r3) : "r"(addr));
}
__device__ __forceinline__ void mma_f16(float* c, const uint32_t* a, const uint32_t* b) {
    asm volatile(
        "mma.sync.aligned.m16n8k16.row.col.f32.f16.f16.f32 "
        "{%0,%1,%2,%3}, {%4,%5,%6,%7}, {%8,%9}, {%0,%1,%2,%3};"
        : "+f"(c[0]), "+f"(c[1]), "+f"(c[2]), "+f"(c[3])
        : "r"(a[0]), "r"(a[1]), "r"(a[2]), "r"(a[3]), "r"(b[0]), "r"(b[1]));
}
__device__ __forceinline__ void cp16(uint32_t s, const void* g) {
    asm volatile("{ .reg .u64 gg; cvta.to.global.u64 gg, %1;"
                 "  cp.async.cg.shared.global [%0], [gg], 16; }"
                 :: "r"(s), "l"(g) : "memory");
}
#define CP_COMMIT() asm volatile("cp.async.commit_group;" ::: "memory")
#define CP_WAIT1()  asm volatile("cp.async.wait_group 1;" ::: "memory")
#define CP_WAIT0()  asm volatile("cp.async.wait_group 0;" ::: "memory")

// ==================== scratch (static device memory; no allocs) ====================
__device__ __half g_x16[(size_t)N_NODES * 64];            // x fp16, node-major
__device__ __half g_wa16[(size_t)KTAPS * 128 * 64];       // [k][o][c64]
__device__ __half g_wb16[(size_t)KTAPS * 2 * 128 * 64];   // [k][ch][o][c64]
__device__ __half g_ws16[(size_t)128 * 64];
__device__ float  g_ya[(size_t)N_NODES * COUT];           // conv_a out fp32, node-major
__device__ __half g_ya16[(size_t)N_NODES * COUT];         // relu(BN_a(ya)) fp16
__device__ float  g_yb[(size_t)COUT * N_NODES];           // conv_b out, ch-major
__device__ float  g_sk[(size_t)COUT * N_NODES];           // skip out,  ch-major
__device__ float  g_stat[2 * COUT];
__device__ float  g_scale_a[COUT];
__device__ float  g_bias_a[COUT];
__device__ float  g_coef[4 * COUT];

// ==================== tiny: zero stat accumulators ====================
__global__ void zero_stat_kernel(float* acc) { acc[threadIdx.x] = 0.f; }

// ==================== x transpose + fp16 convert ====================
__global__ void xconv_kernel(const float* __restrict__ x,
                             __half* __restrict__ x16) {
    __shared__ float tile[32][33];
    int nb = blockIdx.x * 32, cb = blockIdx.y * 32;
    int tx = threadIdx.x, ty = threadIdx.y;
#pragma unroll
    for (int i = 0; i < 4; i++)
        tile[ty + i * 8][tx] = x[(size_t)(cb + ty + i * 8) * N_NODES + nb + tx];
    __syncthreads();
#pragma unroll
    for (int i = 0; i < 4; i++)
        x16[(size_t)(nb + ty + i * 8) * 64 + cb + tx] =
            __float2half_rn(tile[tx][ty + i * 8]);
}

// ==================== weight convert: w[o][c][k] -> fp16 [k][ch64][o][c64] ====================
__global__ void wconv_kernel(const float* __restrict__ w,
                             __half* __restrict__ w16,
                             int C, int K) {
    int i = blockIdx.x * 256 + threadIdx.x;
    int total = 128 * C * K;
    if (i >= total) return;
    int CH = C / 64;
    int cl = i & 63;
    int o  = (i >> 6) & 127;
    int kc = i >> 13;
    int ch = kc % CH;
    int k  = kc / CH;
    int c  = ch * 64 + cl;
    w16[i] = __float2half_rn(w[((size_t)o * C + c) * K + k]);
}

// ==================== gathered conv GEMM on HMMA (fp16, single pass) ====================
// D[node, out] = sum_{k,c} act[node,k,c] * w[out,k,c]
// 8 warps, warp tile 64x32, CC=64 chunk, 3-stage cp.async ring.
template<int CIN, int KT, bool GATHER, bool CHMAJOR>
__global__ __launch_bounds__(256, 1)
void tconv_kernel(const __half* __restrict__ src,
                  const __half* __restrict__ w16,
                  const int* __restrict__ neigh,
                  float* __restrict__ out) {
    constexpr int CH = CIN / 64;
    constexpr int STEPS = KT * CH;
    constexpr int RS = 144;                       // 128 B row + 16 pad
    constexpr uint32_t AH = 0, WH = 18432, BUF = 36864;
    extern __shared__ __align__(16) char smem[];
    const uint32_t sb = smem_to_u32(smem);

    const int t = threadIdx.x;
    const int lane = t & 31, wid = t >> 5;
    const int n_base = blockIdx.x * 128;
    const int warp_m = (wid & 1) * 64;
    const int warp_n = (wid >> 1) * 32;
    const uint32_t aoff_lane = (uint32_t)(warp_m + (lane & 15)) * RS + ((lane & 16) ? 16u : 0u);
    const uint32_t boff_lane = (uint32_t)(warp_n + (lane & 7) + ((lane & 16) ? 8 : 0)) * RS
                               + ((lane & 8) ? 16u : 0u);

    const int row = t >> 1, part = t & 1;

    float acc[4][4][4];
#pragma unroll
    for (int mi = 0; mi < 4; mi++)
#pragma unroll
        for (int ni = 0; ni < 4; ni++)
#pragma unroll
            for (int e = 0; e < 4; e++) acc[mi][ni][e] = 0.f;

    auto j_of = [&](int s) -> int {
        return GATHER ? neigh[(size_t)(n_base + row) * KT + (s / CH)] : (n_base + row);
    };

    auto issue = [&](int s, int j) {
        const uint32_t stg = sb + (uint32_t)(s % 3) * BUF;
        const int k = s / CH, ch = s % CH;
        // activations: row `row`, this thread covers 64 B (32 halfs)
        const __half* ap = src + (size_t)j * CIN + ch * 64 + part * 32;
        const uint32_t ab = stg + AH + (uint32_t)row * RS + part * 64;
#pragma unroll
        for (int i = 0; i < 4; i++)
            cp16(ab + i * 16, ap + i * 8);
        // weights: out-row `row`, 64 B
        const __half* wp = w16 + ((size_t)(k * CH + ch) << 13) + row * 64 + part * 32;
        const uint32_t wb = stg + WH + (uint32_t)row * RS + part * 64;
#pragma unroll
        for (int i = 0; i < 4; i++)
            cp16(wb + i * 16, wp + i * 8);
        CP_COMMIT();
    };

    int jn = j_of(0);
    issue(0, jn);
    if (STEPS > 1) jn = j_of(1);

    for (int s = 0; s < STEPS; ++s) {
        if (s + 1 < STEPS) {
            issue(s + 1, jn);                    // writes buf (s+1)%3 — safe at depth 3
            if (s + 2 < STEPS) jn = j_of(s + 2);
            CP_WAIT1();
        } else {
            CP_WAIT0();
        }
        __syncthreads();

        const uint32_t sbuf = sb + (uint32_t)(s % 3) * BUF;

#pragma unroll
        for (int k16 = 0; k16 < 4; ++k16) {
            const uint32_t kb = (uint32_t)k16 * 32;
            const uint32_t a_h = sbuf + AH + aoff_lane + kb;
            const uint32_t b_h = sbuf + WH + boff_lane + kb;

            uint32_t ah[4][4], bh[4][2];
#pragma unroll
            for (int mi = 0; mi < 4; mi++)
                ldsm_x4(ah[mi][0], ah[mi][1], ah[mi][2], ah[mi][3], a_h + mi * (16 * RS));
#pragma unroll
            for (int nt = 0; nt < 2; nt++) {
                uint32_t r0, r1, r2, r3;
                ldsm_x4(r0, r1, r2, r3, b_h + nt * (16 * RS));
                bh[2 * nt][0] = r0; bh[2 * nt][1] = r1;
                bh[2 * nt + 1][0] = r2; bh[2 * nt + 1][1] = r3;
            }
#pragma unroll
            for (int mi = 0; mi < 4; mi++)
#pragma unroll
                for (int ni = 0; ni < 4; ni++)
                    mma_f16(acc[mi][ni], ah[mi], bh[ni]);
        }
    }

    // ---- epilogue ----
#pragma unroll
    for (int mi = 0; mi < 4; mi++)
#pragma unroll
        for (int ni = 0; ni < 4; ni++) {
            int r = n_base + warp_m + mi * 16 + (lane >> 2);
            int c = warp_n + ni * 8 + (lane & 3) * 2;
            if (CHMAJOR) {
                out[(size_t)c * N_NODES + r]           = acc[mi][ni][0];
                out[(size_t)(c + 1) * N_NODES + r]     = acc[mi][ni][1];
                out[(size_t)c * N_NODES + r + 8]       = acc[mi][ni][2];
                out[(size_t)(c + 1) * N_NODES + r + 8] = acc[mi][ni][3];
            } else {
                *(float2*)&out[(size_t)r * COUT + c] =
                    make_float2(acc[mi][ni][0], acc[mi][ni][1]);
                *(float2*)&out[(size_t)(r + 8) * COUT + c] =
                    make_float2(acc[mi][ni][2], acc[mi][ni][3]);
            }
        }
}

// ==================== BN_a stats: coalesced partial sums + atomics ====================
__global__ void stats_nm_kernel(const float* __restrict__ y, float* __restrict__ acc) {
    const int t = threadIdx.x;
    const int c = t & 127, half = t >> 7;
    const int nb = blockIdx.x * 1024;
    float s = 0.f, q = 0.f;
    for (int n = nb + half; n < nb + 1024; n += 2) {
        float v = y[(size_t)n * COUT + c];
        s += v; q += v * v;
    }
    __shared__ float rs[256], rq[256];
    rs[t] = s; rq[t] = q;
    __syncthreads();
    if (half == 0) {
        atomicAdd(&acc[c],        rs[t] + rs[t + 128]);
        atomicAdd(&acc[COUT + c], rq[t] + rq[t + 128]);
    }
}

// ==================== BN_a finalize ====================
__global__ void stats_fin_kernel(const float* __restrict__ acc,
                                 const float* __restrict__ gamma,
                                 const float* __restrict__ beta,
                                 float* __restrict__ scale,
                                 float* __restrict__ bias) {
    int c = threadIdx.x;
    float mean = acc[c] / N_NODES;
    float var  = acc[COUT + c] / N_NODES - mean * mean;
    float kk   = gamma[c] * rsqrtf(var + BN_EPS);
    scale[c] = kk;
    bias[c]  = beta[c] - kk * mean;
}

// ==================== yaconv: relu(BN_a(ya)) -> fp16 ====================
__global__ void yaconv_kernel(const float* __restrict__ ya,
                              const float* __restrict__ scale,
                              const float* __restrict__ bias,
                              __half* __restrict__ y16) {
    int i = blockIdx.x * 256 + threadIdx.x;      // quad index
    int c0 = (i & 31) * 4;
    float4 v  = ((const float4*)ya)[i];
    float4 sc = *(const float4*)(scale + c0);
    float4 bi = *(const float4*)(bias + c0);
    float a0 = fmaxf(fmaf(v.x, sc.x, bi.x), 0.f);
    float a1 = fmaxf(fmaf(v.y, sc.y, bi.y), 0.f);
    float a2 = fmaxf(fmaf(v.z, sc.z, bi.z), 0.f);
    float a3 = fmaxf(fmaf(v.w, sc.w, bi.w), 0.f);
    ((__half2*)y16)[i * 2]     = __floats2half2_rn(a0, a1);
    ((__half2*)y16)[i * 2 + 1] = __floats2half2_rn(a2, a3);
}

// ==================== BN stats over ch-major yb & sk ====================
__global__ void stats_om_kernel(const float* __restrict__ yb,
                                const float* __restrict__ sk,
                                const float* __restrict__ gb,
                                const float* __restrict__ bb,
                                const float* __restrict__ gs,
                                const float* __restrict__ bs,
                                float* __restrict__ coef) {
    int c = blockIdx.x;
    const float4* pb = (const float4*)(yb + (size_t)c * N_NODES);
    const float4* ps = (const float4*)(sk + (size_t)c * N_NODES);
    float s1 = 0.f, q1 = 0.f, s2 = 0.f, q2 = 0.f;
    for (int i = threadIdx.x; i < N_NODES / 4; i += 256) {
        float4 a = pb[i];
        s1 += a.x + a.y + a.z + a.w;
        q1 += a.x * a.x + a.y * a.y + a.z * a.z + a.w * a.w;
        float4 b = ps[i];
        s2 += b.x + b.y + b.z + b.w;
        q2 += b.x * b.x + b.y * b.y + b.z * b.z + b.w * b.w;
    }
    __shared__ float r1[256], r2[256], r3[256], r4[256];
    r1[threadIdx.x] = s1; r2[threadIdx.x] = q1;
    r3[threadIdx.x] = s2; r4[threadIdx.x] = q2;
    __syncthreads();
    for (int st = 128; st > 0; st >>= 1) {
        if (threadIdx.x < st) {
            r1[threadIdx.x] += r1[threadIdx.x + st];
            r2[threadIdx.x] += r2[threadIdx.x + st];
            r3[threadIdx.x] += r3[threadIdx.x + st];
            r4[threadIdx.x] += r4[threadIdx.x + st];
        }
        __syncthreads();
    }
    if (threadIdx.x == 0) {
        float m1 = r1[0] / N_NODES, v1 = r2[0] / N_NODES - m1 * m1;
        float k1 = gb[c] * rsqrtf(v1 + BN_EPS);
        coef[c]            = k1;
        coef[COUT + c]     = bb[c] - k1 * m1;
        float m2 = r3[0] / N_NODES, v2 = r4[0] / N_NODES - m2 * m2;
        float k2 = gs[c] * rsqrtf(v2 + BN_EPS);
        coef[2 * COUT + c] = k2;
        coef[3 * COUT + c] = bs[c] - k2 * m2;
    }
}

// ==================== final: out = relu(BN_b(yb) + BN_s(sk)) ====================
__global__ void final_ew_kernel(const float* __restrict__ yb,
                                const float* __restrict__ sk,
                                const float* __restrict__ coef,
                                float* __restrict__ out) {
    int i = blockIdx.x * 256 + threadIdx.x;
    int o = i >> 14;
    float sb = coef[o],            bb = coef[COUT + o];
    float ss = coef[2 * COUT + o], bs = coef[3 * COUT + o];
    float4 a = ((const float4*)yb)[i];
    float4 b = ((const float4*)sk)[i];
    float4 r;
    r.x = fmaxf(fmaf(sb, a.x, bb) + fmaf(ss, b.x, bs), 0.f);
    r.y = fmaxf(fmaf(sb, a.y, bb) + fmaf(ss, b.y, bs), 0.f);
    r.z = fmaxf(fmaf(sb, a.z, bb) + fmaf(ss, b.z, bs), 0.f);
    r.w = fmaxf(fmaf(sb, a.w, bb) + fmaf(ss, b.w, bs), 0.f);
    ((float4*)out)[i] = r;
}

// ==================== host ====================
static constexpr int TCONV_SMEM = 3 * 36864;   // 110592 B

extern "C" void kernel_launch(void* const* d_in, const int* in_sizes, int n_in,
                              void* d_out, int out_size) {
    const float* data    = (const float*)d_in[0];
    const int*   neigh   = (const int*)  d_in[1];
    const float* w_a     = (const float*)d_in[2];
    const float* w_b     = (const float*)d_in[3];
    const float* w_skip  = (const float*)d_in[4];
    const float* gamma_a = (const float*)d_in[5];
    const float* beta_a  = (const float*)d_in[6];
    const float* gamma_b = (const float*)d_in[7];
    const float* beta_b  = (const float*)d_in[8];
    const float* gamma_s = (const float*)d_in[9];
    const float* beta_s  = (const float*)d_in[10];
    float* out = (float*)d_out;

    __half *x16, *wa16, *wb16, *ws16, *ya16;
    float *ya, *yb, *sk, *stat, *sca, *bia, *coef;
    cudaGetSymbolAddress((void**)&x16,  g_x16);
    cudaGetSymbolAddress((void**)&wa16, g_wa16);
    cudaGetSymbolAddress((void**)&wb16, g_wb16);
    cudaGetSymbolAddress((void**)&ws16, g_ws16);
    cudaGetSymbolAddress((void**)&ya,   g_ya);
    cudaGetSymbolAddress((void**)&ya16, g_ya16);
    cudaGetSymbolAddress((void**)&yb,   g_yb);
    cudaGetSymbolAddress((void**)&sk,   g_sk);
    cudaGetSymbolAddress((void**)&stat, g_stat);
    cudaGetSymbolAddress((void**)&sca,  g_scale_a);
    cudaGetSymbolAddress((void**)&bia,  g_bias_a);
    cudaGetSymbolAddress((void**)&coef, g_coef);

    auto* ka = tconv_kernel<64, KTAPS, true, false>;
    auto* kb = tconv_kernel<128, KTAPS, true, true>;
    auto* ks = tconv_kernel<64, 1, false, true>;
    cudaFuncSetAttribute(ka, cudaFuncAttributeMaxDynamicSharedMemorySize, TCONV_SMEM);
    cudaFuncSetAttribute(kb, cudaFuncAttributeMaxDynamicSharedMemorySize, TCONV_SMEM);
    cudaFuncSetAttribute(ks, cudaFuncAttributeMaxDynamicSharedMemorySize, TCONV_SMEM);

    // layout transforms + precision converts
    zero_stat_kernel<<<1, 256>>>(stat);
    xconv_kernel<<<dim3(N_NODES / 32, 2), dim3(32, 8)>>>(data, x16);
    wconv_kernel<<<(KTAPS * 64 * 128 + 255) / 256, 256>>>(w_a, wa16, 64, KTAPS);
    wconv_kernel<<<(KTAPS * 128 * 128 + 255) / 256, 256>>>(w_b, wb16, 128, KTAPS);
    wconv_kernel<<<(64 * 128 + 255) / 256, 256>>>(w_skip, ws16, 64, 1);

    const int grid = N_NODES / 128;   // 512

    // conv_a (HMMA fp16 1-pass), node-major fp32 out
    ka<<<grid, 256, TCONV_SMEM>>>(x16, wa16, neigh, ya);
    // BN_a stats + finalize + convert c1 to fp16
    stats_nm_kernel<<<64, 256>>>(ya, stat);
    stats_fin_kernel<<<1, 128>>>(stat, gamma_a, beta_a, sca, bia);
    yaconv_kernel<<<(N_NODES * COUT / 4) / 256, 256>>>(ya, sca, bia, ya16);
    // conv_b, ch-major out
    kb<<<grid, 256, TCONV_SMEM>>>(ya16, wb16, neigh, yb);
    // skip, ch-major out
    ks<<<grid, 256, TCONV_SMEM>>>(x16, ws16, nullptr, sk);
    // BN_b + BN_s stats
    stats_om_kernel<<<COUT, 256>>>(yb, sk, gamma_b, beta_b, gamma_s, beta_s, coef);
    // final elementwise
    final_ew_kernel<<<(COUT * N_NODES / 4) / 256, 256>>>(yb, sk, coef, out);
}